// round 1
// baseline (speedup 1.0000x reference)
#include <cuda_runtime.h>
#include <math.h>

// ---------------------------------------------------------------------------
// LiteTracker correlation pyramid, fp32 SIMT baseline (round 1).
// Pipeline: transpose fmaps -> corr volume X -> GEMM1+GELU -> GEMM2 -> out.
// ---------------------------------------------------------------------------

#define GDIM 7
#define GG 49
#define CDIM 128
#define NPTS 4096
#define NLEV 4

// level geometry
__constant__ int c_H[4]      = {96, 48, 24, 12};
__constant__ int c_W[4]      = {128, 64, 32, 16};
__constant__ int c_pixoff[4] = {0, 12288, 15360, 16128};

// device scratch (allocation-free rule: device globals)
__device__ float g_fmapT[16320 * 128];                         // [pix][c] per level concat
__device__ float g_X[(size_t)NLEV * NPTS * 2401];              // corr volumes
__device__ float g_H[(size_t)NLEV * NPTS * 384];               // hidden acts

// ---------------------------------------------------------------------------
// Kernel T: fmap [128, H, W] -> fmapT [(H*W), 128]
// ---------------------------------------------------------------------------
__global__ void transpose_kernel(const float* __restrict__ src, int HW, int pixoff) {
    __shared__ float tile[32][33];
    int pix0 = blockIdx.x * 32;
    int ch0  = blockIdx.y * 32;
    int tx = threadIdx.x, ty = threadIdx.y;
    int pix = pix0 + tx;
    if (pix < HW) tile[ty][tx] = src[(ch0 + ty) * HW + pix];
    __syncthreads();
    int opix = pix0 + ty;
    int och  = ch0 + tx;
    if (opix < HW) g_fmapT[(size_t)(pixoff + opix) * 128 + och] = tile[tx][ty];
}

// ---------------------------------------------------------------------------
// Kernel C: per (point, level): bilinear support gather + 49x49x128 corr.
// block = 256 threads; grid = (NPTS, NLEV).
// thread tile: 2 hw rows x 5 ij cols  (hwp = t/10 in [0,25), q = t%10)
// ---------------------------------------------------------------------------
__global__ __launch_bounds__(256)
void corr_kernel(const float* __restrict__ coords,
                 const float* __restrict__ tf0, const float* __restrict__ tf1,
                 const float* __restrict__ tf2, const float* __restrict__ tf3) {
    int n = blockIdx.x;
    int L = blockIdx.y;
    const float* tf = (L == 0) ? tf0 : (L == 1) ? tf1 : (L == 2) ? tf2 : tf3;

    float scale = 1.0f / (float)(1 << L);
    float cx = coords[n * 2 + 0] * scale;
    float cy = coords[n * 2 + 1] * scale;

    __shared__ int   s_cidx[GG][4];
    __shared__ float s_cw[GG][4];
    __shared__ float s_feat[GG][36];   // 32-channel chunk, padded
    __shared__ float s_tmpl[GG][36];

    int t = threadIdx.x;

    // corner indices + bilinear weights per support sample (align_corners, zero pad)
    if (t < GG) {
        int h = t / GDIM, w = t % GDIM;            // h -> x offset, w -> y offset
        float fx = cx + (float)(h - 3);
        float fy = cy + (float)(w - 3);
        float x0f = floorf(fx), y0f = floorf(fy);
        float wx = fx - x0f, wy = fy - y0f;
        int x0 = (int)x0f, y0 = (int)y0f;
        int W = c_W[L], Hh = c_H[L];
        int base = c_pixoff[L];
#pragma unroll
        for (int k = 0; k < 4; k++) {
            int xi = x0 + (k & 1);
            int yi = y0 + (k >> 1);
            bool valid = (xi >= 0) && (xi < W) && (yi >= 0) && (yi < Hh);
            float wk = ((k & 1) ? wx : 1.0f - wx) * ((k >> 1) ? wy : 1.0f - wy);
            s_cidx[t][k] = valid ? (base + yi * W + xi) * 128 : 0;
            s_cw[t][k]   = valid ? wk : 0.0f;
        }
    }
    __syncthreads();

    int hwp = t / 10;    // 0..24 active (t < 250)
    int q   = t % 10;
    float acc[2][5];
#pragma unroll
    for (int r = 0; r < 2; r++)
#pragma unroll
        for (int m = 0; m < 5; m++) acc[r][m] = 0.0f;

    for (int c0 = 0; c0 < CDIM; c0 += 32) {
        // template features chunk (coalesced float4)
        for (int idx = t; idx < GG * 8; idx += 256) {
            int ij = idx >> 3;
            int u  = (idx & 7) * 4;
            float4 v = *(const float4*)&tf[((size_t)ij * NPTS + n) * 128 + c0 + u];
            *(float4*)&s_tmpl[ij][u] = v;
        }
        // bilinear-gathered search features chunk
        for (int idx = t; idx < GG * 8; idx += 256) {
            int hw = idx >> 3;
            int u  = (idx & 7) * 4;
            float4 a = make_float4(0.f, 0.f, 0.f, 0.f);
#pragma unroll
            for (int k = 0; k < 4; k++) {
                float wk = s_cw[hw][k];
                float4 v = *(const float4*)&g_fmapT[s_cidx[hw][k] + c0 + u];
                a.x += wk * v.x; a.y += wk * v.y; a.z += wk * v.z; a.w += wk * v.w;
            }
            *(float4*)&s_feat[hw][u] = a;
        }
        __syncthreads();

        if (t < 250) {
            int hw0 = hwp * 2;
            bool has1 = (hw0 + 1) < GG;
#pragma unroll
            for (int u = 0; u < 32; u += 4) {
                float4 f0 = *(const float4*)&s_feat[hw0][u];
                float4 f1 = has1 ? *(const float4*)&s_feat[hw0 + 1][u] : f0;
#pragma unroll
                for (int m = 0; m < 5; m++) {
                    int ij = q + 10 * m;
                    if (ij < GG) {
                        float4 tv = *(const float4*)&s_tmpl[ij][u];
                        acc[0][m] += f0.x * tv.x + f0.y * tv.y + f0.z * tv.z + f0.w * tv.w;
                        acc[1][m] += f1.x * tv.x + f1.y * tv.y + f1.z * tv.z + f1.w * tv.w;
                    }
                }
            }
        }
        __syncthreads();
    }

    if (t < 250) {
        size_t xb = ((size_t)L * NPTS + n) * 2401;
#pragma unroll
        for (int r = 0; r < 2; r++) {
            int hw = hwp * 2 + r;
            if (hw < GG) {
#pragma unroll
                for (int m = 0; m < 5; m++) {
                    int ij = q + 10 * m;
                    if (ij < GG) g_X[xb + hw * 49 + ij] = acc[r][m];
                }
            }
        }
    }
}

// ---------------------------------------------------------------------------
// Tiled fp32 GEMM: C = act(A @ W + bias).  BM=BN=128, BK=8, 8x8 microtile.
// FROM_X: A = g_X (lda 2401) else g_H (lda 384).
// CONCAT: write d_out[row*1024 + L*256 + col], else g_H[(L*4096+row)*384+col].
// ---------------------------------------------------------------------------
template <int KTOT, int LDA, int WN, bool GELU_ACT, bool FROM_X, bool CONCAT>
__global__ __launch_bounds__(256, 2)
void gemm_kernel(const float* __restrict__ Wt, const float* __restrict__ bias,
                 float* __restrict__ Cout) {
    constexpr int BM = 128, BN = 128, BK = 8;
    int m0 = blockIdx.x * BM;
    int n0 = blockIdx.y * BN;
    int L  = blockIdx.z;
    const float* Ab = (FROM_X ? g_X : g_H) + (size_t)L * NPTS * LDA;

    __shared__ float As[BK][BM];
    __shared__ float Bs[BK][BN];

    int t  = threadIdx.x;
    int tn = (t & 15) * 8;
    int tm = (t >> 4) * 8;

    float acc[8][8];
#pragma unroll
    for (int i = 0; i < 8; i++)
#pragma unroll
        for (int j = 0; j < 8; j++) acc[i][j] = 0.0f;

    int a_row = t >> 1;
    int a_k   = (t & 1) * 4;
    int b_k   = t >> 5;
    int b_col = (t & 31) * 4;

    for (int k0 = 0; k0 < KTOT; k0 += BK) {
#pragma unroll
        for (int u = 0; u < 4; u++) {
            int k = k0 + a_k + u;
            As[a_k + u][a_row] = (k < KTOT) ? __ldg(&Ab[(size_t)(m0 + a_row) * LDA + k]) : 0.0f;
        }
        {
            int k = k0 + b_k;
            float4 v = make_float4(0.f, 0.f, 0.f, 0.f);
            if (k < KTOT) v = *(const float4*)&Wt[(size_t)k * WN + n0 + b_col];
            *(float4*)&Bs[b_k][b_col] = v;
        }
        __syncthreads();
#pragma unroll
        for (int k = 0; k < BK; k++) {
            float a[8], b[8];
            *(float4*)(a)     = *(const float4*)&As[k][tm];
            *(float4*)(a + 4) = *(const float4*)&As[k][tm + 4];
            *(float4*)(b)     = *(const float4*)&Bs[k][tn];
            *(float4*)(b + 4) = *(const float4*)&Bs[k][tn + 4];
#pragma unroll
            for (int i = 0; i < 8; i++)
#pragma unroll
                for (int j = 0; j < 8; j++) acc[i][j] += a[i] * b[j];
        }
        __syncthreads();
    }

#pragma unroll
    for (int i = 0; i < 8; i++) {
        int row = m0 + tm + i;
        float outv[8];
#pragma unroll
        for (int j = 0; j < 8; j++) {
            float v = acc[i][j] + bias[n0 + tn + j];
            if (GELU_ACT) v = v * normcdff(v);   // exact GELU: x * Phi(x)
            outv[j] = v;
        }
        float* dst = CONCAT ? &Cout[(size_t)row * 1024 + L * 256 + n0 + tn]
                            : &g_H[((size_t)L * NPTS + row) * 384 + n0 + tn];
        *(float4*)dst       = *(float4*)(outv);
        *(float4*)(dst + 4) = *(float4*)(outv + 4);
    }
}

// ---------------------------------------------------------------------------
// launch
// ---------------------------------------------------------------------------
extern "C" void kernel_launch(void* const* d_in, const int* in_sizes, int n_in,
                              void* d_out, int out_size) {
    (void)out_size;
    const float* fmaps[4] = {nullptr, nullptr, nullptr, nullptr};
    const float* tfeat[4] = {nullptr, nullptr, nullptr, nullptr};
    const float *coords = nullptr, *w1 = nullptr, *b1 = nullptr, *w2 = nullptr, *b2 = nullptr;
    int tc = 0;
    bool seen98 = false;
    for (int i = 0; i < n_in; i++) {
        int s = in_sizes[i];
        const float* p = (const float*)d_in[i];
        if (s == 1572864)       fmaps[0] = p;
        else if (s == 393216)   fmaps[1] = p;
        else if (s == 24576)    fmaps[3] = p;
        else if (s == 25690112) { if (tc < 4) tfeat[tc++] = p; }
        else if (s == 8192)     coords = p;
        else if (s == 921984)   w1 = p;
        else if (s == 384)      b1 = p;
        else if (s == 256)      b2 = p;
        else if (s == 98304)    { if (!seen98) { fmaps[2] = p; seen98 = true; } else w2 = p; }
    }

    static const int hHs[4] = {96, 48, 24, 12};
    static const int hWs[4] = {128, 64, 32, 16};
    static const int hPixOff[4] = {0, 12288, 15360, 16128};

    dim3 tb(32, 32);
    for (int L = 0; L < 4; L++) {
        int HW = hHs[L] * hWs[L];
        transpose_kernel<<<dim3((HW + 31) / 32, 4), tb>>>(fmaps[L], HW, hPixOff[L]);
    }

    corr_kernel<<<dim3(NPTS, NLEV), 256>>>(coords, tfeat[0], tfeat[1], tfeat[2], tfeat[3]);

    // MLP1: X[4096,2401] @ w1[2401,384] + b1 -> GELU -> g_H
    gemm_kernel<2401, 2401, 384, true, true, false>
        <<<dim3(NPTS / 128, 3, NLEV), 256>>>(w1, b1, (float*)d_out);

    // MLP2: H[4096,384] @ w2[384,256] + b2 -> out columns [L*256, L*256+256)
    gemm_kernel<384, 384, 256, false, false, true>
        <<<dim3(NPTS / 128, 2, NLEV), 256>>>(w2, b2, (float*)d_out);
}

// round 3
// speedup vs baseline: 1.6831x; 1.6831x over previous
#include <cuda_runtime.h>
#include <cuda_bf16.h>
#include <mma.h>
#include <cstdint>
#include <math.h>

using namespace nvcuda;

// ---------------------------------------------------------------------------
// LiteTracker correlation pyramid, round 3:
//   transpose -> corr (X as bf16 hi/lo) -> MLP1 WMMA bf16 (3-term hi/lo
//   compensation, fp32 accum, GELU, H as bf16 hi/lo) -> MLP2 WMMA bf16 -> out.
//   (tcgen05 unusable: harness PTX target is base sm_103.)
// ---------------------------------------------------------------------------

#define GDIM 7
#define GG 49
#define CDIM 128
#define NPTS 4096
#define NLEV 4
#define KPAD 2432          // 2401 padded to 76*32
#define HDIM 384
#define ODIM 256

// ------------------------------ level geometry -----------------------------
__constant__ int c_H[4]      = {96, 48, 24, 12};
__constant__ int c_W[4]      = {128, 64, 32, 16};
__constant__ int c_pixoff[4] = {0, 12288, 15360, 16128};

// ------------------------------ device scratch -----------------------------
__device__ __align__(16) float g_fmapT[16320 * 128];
__device__ __align__(16) __nv_bfloat16 g_Xhi[(size_t)NLEV * NPTS * KPAD];
__device__ __align__(16) __nv_bfloat16 g_Xlo[(size_t)NLEV * NPTS * KPAD];
__device__ __align__(16) __nv_bfloat16 g_W1hi[HDIM * KPAD];
__device__ __align__(16) __nv_bfloat16 g_W1lo[HDIM * KPAD];
__device__ __align__(16) __nv_bfloat16 g_W2hi[ODIM * HDIM];
__device__ __align__(16) __nv_bfloat16 g_W2lo[ODIM * HDIM];
__device__ __align__(16) __nv_bfloat16 g_Hhi[(size_t)NLEV * NPTS * HDIM];
__device__ __align__(16) __nv_bfloat16 g_Hlo[(size_t)NLEV * NPTS * HDIM];

// ---------------------------------------------------------------------------
// Kernel T: fmap [128, H, W] -> fmapT [(H*W), 128]
// ---------------------------------------------------------------------------
__global__ void transpose_kernel(const float* __restrict__ src, int HW, int pixoff) {
    __shared__ float tile[32][33];
    int pix0 = blockIdx.x * 32;
    int ch0  = blockIdx.y * 32;
    int tx = threadIdx.x, ty = threadIdx.y;
    int pix = pix0 + tx;
    if (pix < HW) tile[ty][tx] = src[(ch0 + ty) * HW + pix];
    __syncthreads();
    int opix = pix0 + ty;
    int och  = ch0 + tx;
    if (opix < HW) g_fmapT[(size_t)(pixoff + opix) * 128 + och] = tile[tx][ty];
}

// ---------------------------------------------------------------------------
// Weight prep: f32 [K,N] -> bf16 hi/lo [N][Kpad] (transposed, padded)
// ---------------------------------------------------------------------------
__global__ void prep_w1_kernel(const float* __restrict__ w1) {
    int idx = blockIdx.x * 256 + threadIdx.x;
    if (idx >= HDIM * KPAD) return;
    int n = idx / KPAD, k = idx % KPAD;
    float v = (k < 2401) ? w1[k * HDIM + n] : 0.0f;
    __nv_bfloat16 hi = __float2bfloat16(v);
    g_W1hi[idx] = hi;
    g_W1lo[idx] = __float2bfloat16(v - __bfloat162float(hi));
}

__global__ void prep_w2_kernel(const float* __restrict__ w2) {
    int idx = blockIdx.x * 256 + threadIdx.x;
    if (idx >= ODIM * HDIM) return;
    int n = idx / HDIM, k = idx % HDIM;
    float v = w2[k * ODIM + n];
    __nv_bfloat16 hi = __float2bfloat16(v);
    g_W2hi[idx] = hi;
    g_W2lo[idx] = __float2bfloat16(v - __bfloat162float(hi));
}

// ---------------------------------------------------------------------------
// Kernel C: per (point, level) bilinear support gather + 49x49x128 corr.
// Writes X as bf16 hi/lo into [L][N][KPAD] (k >= 2401 zero-padded).
// ---------------------------------------------------------------------------
__global__ __launch_bounds__(256)
void corr_kernel(const float* __restrict__ coords,
                 const float* __restrict__ tf0, const float* __restrict__ tf1,
                 const float* __restrict__ tf2, const float* __restrict__ tf3) {
    int n = blockIdx.x;
    int L = blockIdx.y;
    const float* tf = (L == 0) ? tf0 : (L == 1) ? tf1 : (L == 2) ? tf2 : tf3;

    float scale = 1.0f / (float)(1 << L);
    float cx = coords[n * 2 + 0] * scale;
    float cy = coords[n * 2 + 1] * scale;

    __shared__ int   s_cidx[GG][4];
    __shared__ float s_cw[GG][4];
    __shared__ float s_feat[GG][36];
    __shared__ float s_tmpl[GG][36];

    int t = threadIdx.x;

    if (t < GG) {
        int h = t / GDIM, w = t % GDIM;
        float fx = cx + (float)(h - 3);
        float fy = cy + (float)(w - 3);
        float x0f = floorf(fx), y0f = floorf(fy);
        float wx = fx - x0f, wy = fy - y0f;
        int x0 = (int)x0f, y0 = (int)y0f;
        int W = c_W[L], Hh = c_H[L];
        int base = c_pixoff[L];
#pragma unroll
        for (int k = 0; k < 4; k++) {
            int xi = x0 + (k & 1);
            int yi = y0 + (k >> 1);
            bool valid = (xi >= 0) && (xi < W) && (yi >= 0) && (yi < Hh);
            float wk = ((k & 1) ? wx : 1.0f - wx) * ((k >> 1) ? wy : 1.0f - wy);
            s_cidx[t][k] = valid ? (base + yi * W + xi) * 128 : 0;
            s_cw[t][k]   = valid ? wk : 0.0f;
        }
    }
    __syncthreads();

    int hwp = t / 10;
    int q   = t % 10;
    float acc[2][5];
#pragma unroll
    for (int r = 0; r < 2; r++)
#pragma unroll
        for (int m = 0; m < 5; m++) acc[r][m] = 0.0f;

    for (int c0 = 0; c0 < CDIM; c0 += 32) {
        for (int idx = t; idx < GG * 8; idx += 256) {
            int ij = idx >> 3;
            int u  = (idx & 7) * 4;
            float4 v = *(const float4*)&tf[((size_t)ij * NPTS + n) * 128 + c0 + u];
            *(float4*)&s_tmpl[ij][u] = v;
        }
        for (int idx = t; idx < GG * 8; idx += 256) {
            int hw = idx >> 3;
            int u  = (idx & 7) * 4;
            float4 a = make_float4(0.f, 0.f, 0.f, 0.f);
#pragma unroll
            for (int k = 0; k < 4; k++) {
                float wk = s_cw[hw][k];
                float4 v = *(const float4*)&g_fmapT[s_cidx[hw][k] + c0 + u];
                a.x += wk * v.x; a.y += wk * v.y; a.z += wk * v.z; a.w += wk * v.w;
            }
            *(float4*)&s_feat[hw][u] = a;
        }
        __syncthreads();

        if (t < 250) {
            int hw0 = hwp * 2;
            bool has1 = (hw0 + 1) < GG;
#pragma unroll
            for (int u = 0; u < 32; u += 4) {
                float4 f0 = *(const float4*)&s_feat[hw0][u];
                float4 f1 = has1 ? *(const float4*)&s_feat[hw0 + 1][u] : f0;
#pragma unroll
                for (int m = 0; m < 5; m++) {
                    int ij = q + 10 * m;
                    if (ij < GG) {
                        float4 tv = *(const float4*)&s_tmpl[ij][u];
                        acc[0][m] += f0.x * tv.x + f0.y * tv.y + f0.z * tv.z + f0.w * tv.w;
                        acc[1][m] += f1.x * tv.x + f1.y * tv.y + f1.z * tv.z + f1.w * tv.w;
                    }
                }
            }
        }
        __syncthreads();
    }

    size_t xb = ((size_t)L * NPTS + n) * KPAD;
    if (t < 250) {
#pragma unroll
        for (int r = 0; r < 2; r++) {
            int hw = hwp * 2 + r;
            if (hw < GG) {
#pragma unroll
                for (int m = 0; m < 5; m++) {
                    int ij = q + 10 * m;
                    if (ij < GG) {
                        float v = acc[r][m];
                        __nv_bfloat16 hi = __float2bfloat16(v);
                        g_Xhi[xb + hw * 49 + ij] = hi;
                        g_Xlo[xb + hw * 49 + ij] =
                            __float2bfloat16(v - __bfloat162float(hi));
                    }
                }
            }
        }
    }
    if (t < KPAD - 2401) {
        g_Xhi[xb + 2401 + t] = __float2bfloat16(0.0f);
        g_Xlo[xb + 2401 + t] = __float2bfloat16(0.0f);
    }
}

// ---------------------------------------------------------------------------
// WMMA bf16 GEMM with 3-term hi/lo compensation.
//   MLP1: A=g_X* [L][4096][2432], B=g_W1* [384][2432], GELU -> g_H* (bf16 hi/lo)
//   MLP2: A=g_H* [L][4096][384],  B=g_W2* [256][384],  bias  -> d_out f32
// Block: 128x128 tile, BK=32, 8 warps (warp tile 32x64).
// ---------------------------------------------------------------------------
#define BK 32
#define LDS 40           // BK + 8 pad (bf16 elems)
#define TILE_E (128 * LDS)

template <bool MLP1>
__global__ __launch_bounds__(256)
void wmma_gemm_kernel(const float* __restrict__ bias, float* __restrict__ outp) {
    constexpr int KTOT = MLP1 ? KPAD : HDIM;
    constexpr int NIT  = KTOT / BK;

    __shared__ __align__(16) __nv_bfloat16 smem[4 * TILE_E];
    __nv_bfloat16* sAhi = smem;
    __nv_bfloat16* sAlo = smem + TILE_E;
    __nv_bfloat16* sBhi = smem + 2 * TILE_E;
    __nv_bfloat16* sBlo = smem + 3 * TILE_E;

    int t   = threadIdx.x;
    int wid = t >> 5, lane = t & 31;
    int m0  = blockIdx.x * 128;
    int n0  = blockIdx.y * 128;
    int L   = blockIdx.z;

    const __nv_bfloat16* Ahi = (MLP1 ? g_Xhi : g_Hhi) + ((size_t)L * NPTS + m0) * KTOT;
    const __nv_bfloat16* Alo = (MLP1 ? g_Xlo : g_Hlo) + ((size_t)L * NPTS + m0) * KTOT;
    const __nv_bfloat16* Bhi = (MLP1 ? g_W1hi : g_W2hi) + (size_t)n0 * KTOT;
    const __nv_bfloat16* Blo = (MLP1 ? g_W1lo : g_W2lo) + (size_t)n0 * KTOT;
    const __nv_bfloat16* srcs[4] = {Ahi, Alo, Bhi, Blo};

    // per-thread load geometry: each tile 128 rows x 4 segs of 8 bf16 (16B)
    size_t rowoff[2]; int smoff[2];
#pragma unroll
    for (int j = 0; j < 2; j++) {
        int p = t + 256 * j;
        int row = p >> 2, seg = p & 3;
        rowoff[j] = (size_t)row * KTOT + seg * 8;
        smoff[j]  = row * LDS + seg * 8;
    }

    wmma::fragment<wmma::accumulator, 16, 16, 16, float> acc[2][4];
#pragma unroll
    for (int mi = 0; mi < 2; mi++)
#pragma unroll
        for (int ni = 0; ni < 4; ni++) wmma::fill_fragment(acc[mi][ni], 0.0f);

    int wm = (wid & 3) * 32;    // warp m base
    int wn = (wid >> 2) * 64;   // warp n base

    uint4 pre[8];
#pragma unroll
    for (int tile = 0; tile < 4; tile++)
#pragma unroll
        for (int j = 0; j < 2; j++)
            pre[tile * 2 + j] = *(const uint4*)(srcs[tile] + rowoff[j]);

    for (int kt = 0; kt < NIT; kt++) {
        __syncthreads();
#pragma unroll
        for (int tile = 0; tile < 4; tile++)
#pragma unroll
            for (int j = 0; j < 2; j++)
                *(uint4*)(smem + tile * TILE_E + smoff[j]) = pre[tile * 2 + j];
        __syncthreads();

        if (kt + 1 < NIT) {
            int kc = (kt + 1) * BK;
#pragma unroll
            for (int tile = 0; tile < 4; tile++)
#pragma unroll
                for (int j = 0; j < 2; j++)
                    pre[tile * 2 + j] = *(const uint4*)(srcs[tile] + kc + rowoff[j]);
        }

#pragma unroll
        for (int kk = 0; kk < 2; kk++) {
            wmma::fragment<wmma::matrix_a, 16, 16, 16, __nv_bfloat16, wmma::row_major> ah[2], al[2];
            wmma::fragment<wmma::matrix_b, 16, 16, 16, __nv_bfloat16, wmma::col_major> bh[4], bl[4];
#pragma unroll
            for (int mi = 0; mi < 2; mi++) {
                wmma::load_matrix_sync(ah[mi], sAhi + (wm + mi * 16) * LDS + kk * 16, LDS);
                wmma::load_matrix_sync(al[mi], sAlo + (wm + mi * 16) * LDS + kk * 16, LDS);
            }
#pragma unroll
            for (int ni = 0; ni < 4; ni++) {
                wmma::load_matrix_sync(bh[ni], sBhi + (wn + ni * 16) * LDS + kk * 16, LDS);
                wmma::load_matrix_sync(bl[ni], sBlo + (wn + ni * 16) * LDS + kk * 16, LDS);
            }
#pragma unroll
            for (int mi = 0; mi < 2; mi++)
#pragma unroll
                for (int ni = 0; ni < 4; ni++) {
                    wmma::mma_sync(acc[mi][ni], ah[mi], bh[ni], acc[mi][ni]);
                    wmma::mma_sync(acc[mi][ni], al[mi], bh[ni], acc[mi][ni]);
                    wmma::mma_sync(acc[mi][ni], ah[mi], bl[ni], acc[mi][ni]);
                }
        }
    }
    __syncthreads();

    // epilogue via per-warp smem staging (reuse tile smem)
    float* stage = (float*)smem + wid * 256;
    int r = lane >> 1;
    int c = (lane & 1) * 8;
#pragma unroll
    for (int mi = 0; mi < 2; mi++)
#pragma unroll
        for (int ni = 0; ni < 4; ni++) {
            wmma::store_matrix_sync(stage, acc[mi][ni], 16, wmma::mem_row_major);
            __syncwarp();
            int grow = m0 + wm + mi * 16 + r;
            int gcol = n0 + wn + ni * 16 + c;
            float v[8];
#pragma unroll
            for (int u = 0; u < 8; u++) {
                float x = stage[r * 16 + c + u] + bias[gcol + u];
                if (MLP1) x = x * normcdff(x);   // exact GELU
                v[u] = x;
            }
            if (MLP1) {
                __nv_bfloat16 hi8[8], lo8[8];
#pragma unroll
                for (int u = 0; u < 8; u++) {
                    __nv_bfloat16 hi = __float2bfloat16(v[u]);
                    hi8[u] = hi;
                    lo8[u] = __float2bfloat16(v[u] - __bfloat162float(hi));
                }
                size_t hidx = ((size_t)L * NPTS + grow) * HDIM + gcol;
                *(uint4*)&g_Hhi[hidx] = *(uint4*)hi8;
                *(uint4*)&g_Hlo[hidx] = *(uint4*)lo8;
            } else {
                float* dst = &outp[(size_t)grow * 1024 + L * ODIM + gcol];
                *(float4*)dst       = *(float4*)(v);
                *(float4*)(dst + 4) = *(float4*)(v + 4);
            }
            __syncwarp();
        }
}

// ---------------------------------------------------------------------------
// launch
// ---------------------------------------------------------------------------
extern "C" void kernel_launch(void* const* d_in, const int* in_sizes, int n_in,
                              void* d_out, int out_size) {
    (void)out_size;
    const float* fmaps[4] = {nullptr, nullptr, nullptr, nullptr};
    const float* tfeat[4] = {nullptr, nullptr, nullptr, nullptr};
    const float *coords = nullptr, *w1 = nullptr, *b1 = nullptr, *w2 = nullptr, *b2 = nullptr;
    int tc = 0;
    bool seen98 = false;
    for (int i = 0; i < n_in; i++) {
        int s = in_sizes[i];
        const float* p = (const float*)d_in[i];
        if (s == 1572864)       fmaps[0] = p;
        else if (s == 393216)   fmaps[1] = p;
        else if (s == 24576)    fmaps[3] = p;
        else if (s == 25690112) { if (tc < 4) tfeat[tc++] = p; }
        else if (s == 8192)     coords = p;
        else if (s == 921984)   w1 = p;
        else if (s == 384)      b1 = p;
        else if (s == 256)      b2 = p;
        else if (s == 98304)    { if (!seen98) { fmaps[2] = p; seen98 = true; } else w2 = p; }
    }

    static const int hHs[4] = {96, 48, 24, 12};
    static const int hWs[4] = {128, 64, 32, 16};
    static const int hPixOff[4] = {0, 12288, 15360, 16128};

    dim3 tb(32, 32);
    for (int L = 0; L < 4; L++) {
        int HW = hHs[L] * hWs[L];
        transpose_kernel<<<dim3((HW + 31) / 32, 4), tb>>>(fmaps[L], HW, hPixOff[L]);
    }

    prep_w1_kernel<<<(HDIM * KPAD + 255) / 256, 256>>>(w1);
    prep_w2_kernel<<<(ODIM * HDIM + 255) / 256, 256>>>(w2);

    corr_kernel<<<dim3(NPTS, NLEV), 256>>>(coords, tfeat[0], tfeat[1], tfeat[2], tfeat[3]);

    // MLP1: X @ w1 + b1 -> GELU -> H (bf16 hi/lo)
    wmma_gemm_kernel<true><<<dim3(NPTS / 128, HDIM / 128, NLEV), 256>>>(b1, nullptr);

    // MLP2: H @ w2 + b2 -> out columns [L*256, (L+1)*256)
    wmma_gemm_kernel<false><<<dim3(NPTS / 128, ODIM / 128, NLEV), 256>>>(b2, (float*)d_out);
}

// round 4
// speedup vs baseline: 2.1903x; 1.3013x over previous
#include <cuda_runtime.h>
#include <cuda_bf16.h>
#include <mma.h>
#include <cstdint>
#include <math.h>

using namespace nvcuda;

// ---------------------------------------------------------------------------
// LiteTracker correlation pyramid, round 4:
//   transpose -> corr on WMMA bf16 (hi/lo, padded 64x64 per point) -> MLP1
//   WMMA bf16 (3-term hi/lo, GELU) -> MLP2 WMMA bf16 -> out.
// ---------------------------------------------------------------------------

#define GDIM 7
#define GG 49
#define CDIM 128
#define NPTS 4096
#define NLEV 4
#define KPAD 2432          // 2401 padded to 76*32
#define HDIM 384
#define ODIM 256

// ------------------------------ level geometry -----------------------------
__constant__ int c_H[4]      = {96, 48, 24, 12};
__constant__ int c_W[4]      = {128, 64, 32, 16};
__constant__ int c_pixoff[4] = {0, 12288, 15360, 16128};

// ------------------------------ device scratch -----------------------------
__device__ __align__(16) float g_fmapT[16320 * 128];
__device__ __align__(16) __nv_bfloat16 g_Xhi[(size_t)NLEV * NPTS * KPAD];
__device__ __align__(16) __nv_bfloat16 g_Xlo[(size_t)NLEV * NPTS * KPAD];
__device__ __align__(16) __nv_bfloat16 g_W1hi[HDIM * KPAD];
__device__ __align__(16) __nv_bfloat16 g_W1lo[HDIM * KPAD];
__device__ __align__(16) __nv_bfloat16 g_W2hi[ODIM * HDIM];
__device__ __align__(16) __nv_bfloat16 g_W2lo[ODIM * HDIM];
__device__ __align__(16) __nv_bfloat16 g_Hhi[(size_t)NLEV * NPTS * HDIM];
__device__ __align__(16) __nv_bfloat16 g_Hlo[(size_t)NLEV * NPTS * HDIM];

// ---------------------------------------------------------------------------
// Kernel T: fmap [128, H, W] -> fmapT [(H*W), 128]
// ---------------------------------------------------------------------------
__global__ void transpose_kernel(const float* __restrict__ src, int HW, int pixoff) {
    __shared__ float tile[32][33];
    int pix0 = blockIdx.x * 32;
    int ch0  = blockIdx.y * 32;
    int tx = threadIdx.x, ty = threadIdx.y;
    int pix = pix0 + tx;
    if (pix < HW) tile[ty][tx] = src[(ch0 + ty) * HW + pix];
    __syncthreads();
    int opix = pix0 + ty;
    int och  = ch0 + tx;
    if (opix < HW) g_fmapT[(size_t)(pixoff + opix) * 128 + och] = tile[tx][ty];
}

// ---------------------------------------------------------------------------
// Weight prep
// ---------------------------------------------------------------------------
__global__ void prep_w1_kernel(const float* __restrict__ w1) {
    int idx = blockIdx.x * 256 + threadIdx.x;
    if (idx >= HDIM * KPAD) return;
    int n = idx / KPAD, k = idx % KPAD;
    float v = (k < 2401) ? w1[k * HDIM + n] : 0.0f;
    __nv_bfloat16 hi = __float2bfloat16(v);
    g_W1hi[idx] = hi;
    g_W1lo[idx] = __float2bfloat16(v - __bfloat162float(hi));
}

__global__ void prep_w2_kernel(const float* __restrict__ w2) {
    int idx = blockIdx.x * 256 + threadIdx.x;
    if (idx >= ODIM * HDIM) return;
    int n = idx / HDIM, k = idx % HDIM;
    float v = w2[k * ODIM + n];
    __nv_bfloat16 hi = __float2bfloat16(v);
    g_W2hi[idx] = hi;
    g_W2lo[idx] = __float2bfloat16(v - __bfloat162float(hi));
}

// ---------------------------------------------------------------------------
// Kernel C (WMMA): per (point, level): bilinear support gather + 49x49x128
// correlation on tensor cores (bf16 hi/lo, fp32 accum, 3-term compensation).
// smem tiles padded to 64 rows; padded rows/cols of C are discarded, so no
// zero-init is required.
// ---------------------------------------------------------------------------
#define CLDS 136                   // 128 + 8 pad (bf16 elems)
#define CTILE (64 * CLDS)          // one 64x128 tile (elems)
#define CORR_SMEM (4 * CTILE * 2)  // bytes: Ahi, Alo, Bhi, Blo

__global__ __launch_bounds__(256)
void corr_wmma_kernel(const float* __restrict__ coords,
                      const float* __restrict__ tf0, const float* __restrict__ tf1,
                      const float* __restrict__ tf2, const float* __restrict__ tf3) {
    extern __shared__ __align__(16) __nv_bfloat16 csmem[];
    __nv_bfloat16* sAhi = csmem;
    __nv_bfloat16* sAlo = csmem + CTILE;
    __nv_bfloat16* sBhi = csmem + 2 * CTILE;
    __nv_bfloat16* sBlo = csmem + 3 * CTILE;

    __shared__ int   s_cidx[GG][4];
    __shared__ float s_cw[GG][4];

    int n = blockIdx.x;
    int L = blockIdx.y;
    const float* tf = (L == 0) ? tf0 : (L == 1) ? tf1 : (L == 2) ? tf2 : tf3;

    int t = threadIdx.x;
    int wid = t >> 5, lane = t & 31;

    // corner indices + bilinear weights (h -> x offset, w -> y offset)
    if (t < GG) {
        float scale = 1.0f / (float)(1 << L);
        float cx = coords[n * 2 + 0] * scale;
        float cy = coords[n * 2 + 1] * scale;
        int h = t / GDIM, w = t % GDIM;
        float fx = cx + (float)(h - 3);
        float fy = cy + (float)(w - 3);
        float x0f = floorf(fx), y0f = floorf(fy);
        float wx = fx - x0f, wy = fy - y0f;
        int x0 = (int)x0f, y0 = (int)y0f;
        int W = c_W[L], Hh = c_H[L];
        int base = c_pixoff[L];
#pragma unroll
        for (int k = 0; k < 4; k++) {
            int xi = x0 + (k & 1);
            int yi = y0 + (k >> 1);
            bool valid = (xi >= 0) && (xi < W) && (yi >= 0) && (yi < Hh);
            float wk = ((k & 1) ? wx : 1.0f - wx) * ((k >> 1) ? wy : 1.0f - wy);
            s_cidx[t][k] = valid ? (base + yi * W + xi) * 128 : 0;
            s_cw[t][k]   = valid ? wk : 0.0f;
        }
    }
    __syncthreads();

    // B tile: tfeat rows (49 x 128 f32 -> bf16 hi/lo). 49*32 float4 chunks.
    for (int idx = t; idx < GG * 32; idx += 256) {
        int row = idx >> 5;
        int seg = (idx & 31) * 4;
        float4 v = *(const float4*)&tf[((size_t)row * NPTS + n) * 128 + seg];
        __nv_bfloat16 h0 = __float2bfloat16(v.x), h1 = __float2bfloat16(v.y);
        __nv_bfloat16 h2 = __float2bfloat16(v.z), h3 = __float2bfloat16(v.w);
        __nv_bfloat16* bh = &sBhi[row * CLDS + seg];
        __nv_bfloat16* bl = &sBlo[row * CLDS + seg];
        bh[0] = h0; bh[1] = h1; bh[2] = h2; bh[3] = h3;
        bl[0] = __float2bfloat16(v.x - __bfloat162float(h0));
        bl[1] = __float2bfloat16(v.y - __bfloat162float(h1));
        bl[2] = __float2bfloat16(v.z - __bfloat162float(h2));
        bl[3] = __float2bfloat16(v.w - __bfloat162float(h3));
    }

    // A tile: bilinear-gathered support features (49 unique samples share one
    // fractional offset -> only 8x8 unique fmap pixels; L1-resident).
    for (int idx = t; idx < GG * 32; idx += 256) {
        int row = idx >> 5;
        int seg = (idx & 31) * 4;
        float4 a = make_float4(0.f, 0.f, 0.f, 0.f);
#pragma unroll
        for (int k = 0; k < 4; k++) {
            float wk = s_cw[row][k];
            float4 v = *(const float4*)&g_fmapT[s_cidx[row][k] + seg];
            a.x += wk * v.x; a.y += wk * v.y; a.z += wk * v.z; a.w += wk * v.w;
        }
        __nv_bfloat16 h0 = __float2bfloat16(a.x), h1 = __float2bfloat16(a.y);
        __nv_bfloat16 h2 = __float2bfloat16(a.z), h3 = __float2bfloat16(a.w);
        __nv_bfloat16* ah = &sAhi[row * CLDS + seg];
        __nv_bfloat16* al = &sAlo[row * CLDS + seg];
        ah[0] = h0; ah[1] = h1; ah[2] = h2; ah[3] = h3;
        al[0] = __float2bfloat16(a.x - __bfloat162float(h0));
        al[1] = __float2bfloat16(a.y - __bfloat162float(h1));
        al[2] = __float2bfloat16(a.z - __bfloat162float(h2));
        al[3] = __float2bfloat16(a.w - __bfloat162float(h3));
    }
    __syncthreads();

    // MMA: C[64x64] = Ahi*Bhi^T + Alo*Bhi^T + Ahi*Blo^T.
    // warp wid: rows wm = (wid&3)*16, cols wn = (wid>>2)*32 (2 col tiles).
    int wm = (wid & 3) * 16;
    int wn = (wid >> 2) * 32;
    wmma::fragment<wmma::accumulator, 16, 16, 16, float> acc[2];
    wmma::fill_fragment(acc[0], 0.0f);
    wmma::fill_fragment(acc[1], 0.0f);

#pragma unroll
    for (int ks = 0; ks < 8; ks++) {
        wmma::fragment<wmma::matrix_a, 16, 16, 16, __nv_bfloat16, wmma::row_major> ah, al;
        wmma::load_matrix_sync(ah, sAhi + wm * CLDS + ks * 16, CLDS);
        wmma::load_matrix_sync(al, sAlo + wm * CLDS + ks * 16, CLDS);
#pragma unroll
        for (int ni = 0; ni < 2; ni++) {
            wmma::fragment<wmma::matrix_b, 16, 16, 16, __nv_bfloat16, wmma::col_major> bh, bl;
            wmma::load_matrix_sync(bh, sBhi + (wn + ni * 16) * CLDS + ks * 16, CLDS);
            wmma::load_matrix_sync(bl, sBlo + (wn + ni * 16) * CLDS + ks * 16, CLDS);
            wmma::mma_sync(acc[ni], ah, bh, acc[ni]);
            wmma::mma_sync(acc[ni], al, bh, acc[ni]);
            wmma::mma_sync(acc[ni], ah, bl, acc[ni]);
        }
    }
    __syncthreads();

    // stage C (reuse sAhi region: 64x68 f32 = 17408 B == one tile buffer)
    float* stage = (float*)sAhi;
#pragma unroll
    for (int ni = 0; ni < 2; ni++)
        wmma::store_matrix_sync(stage + wm * 68 + wn + ni * 16, acc[ni], 68,
                                wmma::mem_row_major);
    __syncthreads();

    // write X row (2401 elems) as bf16 hi/lo; pad cols [2401,2432) with zeros
    size_t xb = ((size_t)L * NPTS + n) * KPAD;
    for (int idx = t; idx < 2401; idx += 256) {
        int hw = idx / 49, ij = idx - hw * 49;
        float v = stage[hw * 68 + ij];
        __nv_bfloat16 hi = __float2bfloat16(v);
        g_Xhi[xb + idx] = hi;
        g_Xlo[xb + idx] = __float2bfloat16(v - __bfloat162float(hi));
    }
    if (t < KPAD - 2401) {
        g_Xhi[xb + 2401 + t] = __float2bfloat16(0.0f);
        g_Xlo[xb + 2401 + t] = __float2bfloat16(0.0f);
    }
    (void)lane;
}

// ---------------------------------------------------------------------------
// WMMA bf16 GEMM with 3-term hi/lo compensation (MLP1 / MLP2), unchanged.
// ---------------------------------------------------------------------------
#define BK 32
#define LDS 40
#define TILE_E (128 * LDS)

template <bool MLP1>
__global__ __launch_bounds__(256)
void wmma_gemm_kernel(const float* __restrict__ bias, float* __restrict__ outp) {
    constexpr int KTOT = MLP1 ? KPAD : HDIM;
    constexpr int NIT  = KTOT / BK;

    __shared__ __align__(16) __nv_bfloat16 smem[4 * TILE_E];
    __nv_bfloat16* sAhi = smem;
    __nv_bfloat16* sAlo = smem + TILE_E;
    __nv_bfloat16* sBhi = smem + 2 * TILE_E;
    __nv_bfloat16* sBlo = smem + 3 * TILE_E;

    int t   = threadIdx.x;
    int wid = t >> 5, lane = t & 31;
    int m0  = blockIdx.x * 128;
    int n0  = blockIdx.y * 128;
    int L   = blockIdx.z;

    const __nv_bfloat16* Ahi = (MLP1 ? g_Xhi : g_Hhi) + ((size_t)L * NPTS + m0) * KTOT;
    const __nv_bfloat16* Alo = (MLP1 ? g_Xlo : g_Hlo) + ((size_t)L * NPTS + m0) * KTOT;
    const __nv_bfloat16* Bhi = (MLP1 ? g_W1hi : g_W2hi) + (size_t)n0 * KTOT;
    const __nv_bfloat16* Blo = (MLP1 ? g_W1lo : g_W2lo) + (size_t)n0 * KTOT;
    const __nv_bfloat16* srcs[4] = {Ahi, Alo, Bhi, Blo};

    size_t rowoff[2]; int smoff[2];
#pragma unroll
    for (int j = 0; j < 2; j++) {
        int p = t + 256 * j;
        int row = p >> 2, seg = p & 3;
        rowoff[j] = (size_t)row * KTOT + seg * 8;
        smoff[j]  = row * LDS + seg * 8;
    }

    wmma::fragment<wmma::accumulator, 16, 16, 16, float> acc[2][4];
#pragma unroll
    for (int mi = 0; mi < 2; mi++)
#pragma unroll
        for (int ni = 0; ni < 4; ni++) wmma::fill_fragment(acc[mi][ni], 0.0f);

    int wm = (wid & 3) * 32;
    int wn = (wid >> 2) * 64;

    uint4 pre[8];
#pragma unroll
    for (int tile = 0; tile < 4; tile++)
#pragma unroll
        for (int j = 0; j < 2; j++)
            pre[tile * 2 + j] = *(const uint4*)(srcs[tile] + rowoff[j]);

    for (int kt = 0; kt < NIT; kt++) {
        __syncthreads();
#pragma unroll
        for (int tile = 0; tile < 4; tile++)
#pragma unroll
            for (int j = 0; j < 2; j++)
                *(uint4*)(smem + tile * TILE_E + smoff[j]) = pre[tile * 2 + j];
        __syncthreads();

        if (kt + 1 < NIT) {
            int kc = (kt + 1) * BK;
#pragma unroll
            for (int tile = 0; tile < 4; tile++)
#pragma unroll
                for (int j = 0; j < 2; j++)
                    pre[tile * 2 + j] = *(const uint4*)(srcs[tile] + kc + rowoff[j]);
        }

#pragma unroll
        for (int kk = 0; kk < 2; kk++) {
            wmma::fragment<wmma::matrix_a, 16, 16, 16, __nv_bfloat16, wmma::row_major> ah[2], al[2];
            wmma::fragment<wmma::matrix_b, 16, 16, 16, __nv_bfloat16, wmma::col_major> bh[4], bl[4];
#pragma unroll
            for (int mi = 0; mi < 2; mi++) {
                wmma::load_matrix_sync(ah[mi], sAhi + (wm + mi * 16) * LDS + kk * 16, LDS);
                wmma::load_matrix_sync(al[mi], sAlo + (wm + mi * 16) * LDS + kk * 16, LDS);
            }
#pragma unroll
            for (int ni = 0; ni < 4; ni++) {
                wmma::load_matrix_sync(bh[ni], sBhi + (wn + ni * 16) * LDS + kk * 16, LDS);
                wmma::load_matrix_sync(bl[ni], sBlo + (wn + ni * 16) * LDS + kk * 16, LDS);
            }
#pragma unroll
            for (int mi = 0; mi < 2; mi++)
#pragma unroll
                for (int ni = 0; ni < 4; ni++) {
                    wmma::mma_sync(acc[mi][ni], ah[mi], bh[ni], acc[mi][ni]);
                    wmma::mma_sync(acc[mi][ni], al[mi], bh[ni], acc[mi][ni]);
                    wmma::mma_sync(acc[mi][ni], ah[mi], bl[ni], acc[mi][ni]);
                }
        }
    }
    __syncthreads();

    float* stage = (float*)smem + wid * 256;
    int r = lane >> 1;
    int c = (lane & 1) * 8;
#pragma unroll
    for (int mi = 0; mi < 2; mi++)
#pragma unroll
        for (int ni = 0; ni < 4; ni++) {
            wmma::store_matrix_sync(stage, acc[mi][ni], 16, wmma::mem_row_major);
            __syncwarp();
            int grow = m0 + wm + mi * 16 + r;
            int gcol = n0 + wn + ni * 16 + c;
            float v[8];
#pragma unroll
            for (int u = 0; u < 8; u++) {
                float x = stage[r * 16 + c + u] + bias[gcol + u];
                if (MLP1) x = x * normcdff(x);
                v[u] = x;
            }
            if (MLP1) {
                __nv_bfloat16 hi8[8], lo8[8];
#pragma unroll
                for (int u = 0; u < 8; u++) {
                    __nv_bfloat16 hi = __float2bfloat16(v[u]);
                    hi8[u] = hi;
                    lo8[u] = __float2bfloat16(v[u] - __bfloat162float(hi));
                }
                size_t hidx = ((size_t)L * NPTS + grow) * HDIM + gcol;
                *(uint4*)&g_Hhi[hidx] = *(uint4*)hi8;
                *(uint4*)&g_Hlo[hidx] = *(uint4*)lo8;
            } else {
                float* dst = &outp[(size_t)grow * 1024 + L * ODIM + gcol];
                *(float4*)dst       = *(float4*)(v);
                *(float4*)(dst + 4) = *(float4*)(v + 4);
            }
            __syncwarp();
        }
}

// ---------------------------------------------------------------------------
// launch
// ---------------------------------------------------------------------------
extern "C" void kernel_launch(void* const* d_in, const int* in_sizes, int n_in,
                              void* d_out, int out_size) {
    (void)out_size;
    const float* fmaps[4] = {nullptr, nullptr, nullptr, nullptr};
    const float* tfeat[4] = {nullptr, nullptr, nullptr, nullptr};
    const float *coords = nullptr, *w1 = nullptr, *b1 = nullptr, *w2 = nullptr, *b2 = nullptr;
    int tc = 0;
    bool seen98 = false;
    for (int i = 0; i < n_in; i++) {
        int s = in_sizes[i];
        const float* p = (const float*)d_in[i];
        if (s == 1572864)       fmaps[0] = p;
        else if (s == 393216)   fmaps[1] = p;
        else if (s == 24576)    fmaps[3] = p;
        else if (s == 25690112) { if (tc < 4) tfeat[tc++] = p; }
        else if (s == 8192)     coords = p;
        else if (s == 921984)   w1 = p;
        else if (s == 384)      b1 = p;
        else if (s == 256)      b2 = p;
        else if (s == 98304)    { if (!seen98) { fmaps[2] = p; seen98 = true; } else w2 = p; }
    }

    static const int hHs[4] = {96, 48, 24, 12};
    static const int hWs[4] = {128, 64, 32, 16};
    static const int hPixOff[4] = {0, 12288, 15360, 16128};

    cudaFuncSetAttribute(corr_wmma_kernel,
                         cudaFuncAttributeMaxDynamicSharedMemorySize, CORR_SMEM);

    dim3 tb(32, 32);
    for (int L = 0; L < 4; L++) {
        int HW = hHs[L] * hWs[L];
        transpose_kernel<<<dim3((HW + 31) / 32, 4), tb>>>(fmaps[L], HW, hPixOff[L]);
    }

    prep_w1_kernel<<<(HDIM * KPAD + 255) / 256, 256>>>(w1);
    prep_w2_kernel<<<(ODIM * HDIM + 255) / 256, 256>>>(w2);

    corr_wmma_kernel<<<dim3(NPTS, NLEV), 256, CORR_SMEM>>>(
        coords, tfeat[0], tfeat[1], tfeat[2], tfeat[3]);

    wmma_gemm_kernel<true><<<dim3(NPTS / 128, HDIM / 128, NLEV), 256>>>(b1, nullptr);

    wmma_gemm_kernel<false><<<dim3(NPTS / 128, ODIM / 128, NLEV), 256>>>(b2, (float*)d_out);
}

// round 5
// speedup vs baseline: 2.3623x; 1.0785x over previous
#include <cuda_runtime.h>
#include <cuda_bf16.h>
#include <mma.h>
#include <cstdint>
#include <math.h>

using namespace nvcuda;

// ---------------------------------------------------------------------------
// LiteTracker correlation pyramid, round 5:
//   transpose -> corr WMMA bf16 (hi/lo) -> MLP1 WMMA + cp.async 2-stage
//   pipeline -> MLP2 same template -> out.
// ---------------------------------------------------------------------------

#define GDIM 7
#define GG 49
#define CDIM 128
#define NPTS 4096
#define NLEV 4
#define KPAD 2432          // 2401 padded to 76*32
#define HDIM 384
#define ODIM 256

// ------------------------------ level geometry -----------------------------
__constant__ int c_H[4]      = {96, 48, 24, 12};
__constant__ int c_W[4]      = {128, 64, 32, 16};
__constant__ int c_pixoff[4] = {0, 12288, 15360, 16128};

// ------------------------------ device scratch -----------------------------
__device__ __align__(16) float g_fmapT[16320 * 128];
__device__ __align__(16) __nv_bfloat16 g_Xhi[(size_t)NLEV * NPTS * KPAD];
__device__ __align__(16) __nv_bfloat16 g_Xlo[(size_t)NLEV * NPTS * KPAD];
__device__ __align__(16) __nv_bfloat16 g_W1hi[HDIM * KPAD];
__device__ __align__(16) __nv_bfloat16 g_W1lo[HDIM * KPAD];
__device__ __align__(16) __nv_bfloat16 g_W2hi[ODIM * HDIM];
__device__ __align__(16) __nv_bfloat16 g_W2lo[ODIM * HDIM];
__device__ __align__(16) __nv_bfloat16 g_Hhi[(size_t)NLEV * NPTS * HDIM];
__device__ __align__(16) __nv_bfloat16 g_Hlo[(size_t)NLEV * NPTS * HDIM];

// ------------------------------ cp.async helpers ---------------------------
__device__ __forceinline__ uint32_t smem_to_u32(const void* p) {
    uint32_t a;
    asm("{ .reg .u64 t; cvta.to.shared.u64 t, %1; cvt.u32.u64 %0, t; }"
        : "=r"(a) : "l"(p));
    return a;
}
__device__ __forceinline__ void cp16(uint32_t dst, const void* src) {
    asm volatile("cp.async.cg.shared.global [%0], [%1], 16;" :: "r"(dst), "l"(src));
}
#define CP_COMMIT() asm volatile("cp.async.commit_group;" ::: "memory")
#define CP_WAIT0()  asm volatile("cp.async.wait_group 0;" ::: "memory")

// ---------------------------------------------------------------------------
// Kernel T: fmap [128, H, W] -> fmapT [(H*W), 128]
// ---------------------------------------------------------------------------
__global__ void transpose_kernel(const float* __restrict__ src, int HW, int pixoff) {
    __shared__ float tile[32][33];
    int pix0 = blockIdx.x * 32;
    int ch0  = blockIdx.y * 32;
    int tx = threadIdx.x, ty = threadIdx.y;
    int pix = pix0 + tx;
    if (pix < HW) tile[ty][tx] = src[(ch0 + ty) * HW + pix];
    __syncthreads();
    int opix = pix0 + ty;
    int och  = ch0 + tx;
    if (opix < HW) g_fmapT[(size_t)(pixoff + opix) * 128 + och] = tile[tx][ty];
}

// ---------------------------------------------------------------------------
// Weight prep
// ---------------------------------------------------------------------------
__global__ void prep_w1_kernel(const float* __restrict__ w1) {
    int idx = blockIdx.x * 256 + threadIdx.x;
    if (idx >= HDIM * KPAD) return;
    int n = idx / KPAD, k = idx % KPAD;
    float v = (k < 2401) ? w1[k * HDIM + n] : 0.0f;
    __nv_bfloat16 hi = __float2bfloat16(v);
    g_W1hi[idx] = hi;
    g_W1lo[idx] = __float2bfloat16(v - __bfloat162float(hi));
}

__global__ void prep_w2_kernel(const float* __restrict__ w2) {
    int idx = blockIdx.x * 256 + threadIdx.x;
    if (idx >= ODIM * HDIM) return;
    int n = idx / HDIM, k = idx % HDIM;
    float v = w2[k * ODIM + n];
    __nv_bfloat16 hi = __float2bfloat16(v);
    g_W2hi[idx] = hi;
    g_W2lo[idx] = __float2bfloat16(v - __bfloat162float(hi));
}

// ---------------------------------------------------------------------------
// Kernel C (WMMA): per (point, level): bilinear support gather + 49x49x128
// correlation on tensor cores (bf16 hi/lo, fp32 accum, 3-term compensation).
// ---------------------------------------------------------------------------
#define CLDS 136                   // 128 + 8 pad (bf16 elems)
#define CTILE (64 * CLDS)          // one 64x128 tile (elems)
#define CORR_SMEM (4 * CTILE * 2)  // bytes

__global__ __launch_bounds__(256)
void corr_wmma_kernel(const float* __restrict__ coords,
                      const float* __restrict__ tf0, const float* __restrict__ tf1,
                      const float* __restrict__ tf2, const float* __restrict__ tf3) {
    extern __shared__ __align__(16) __nv_bfloat16 csmem[];
    __nv_bfloat16* sAhi = csmem;
    __nv_bfloat16* sAlo = csmem + CTILE;
    __nv_bfloat16* sBhi = csmem + 2 * CTILE;
    __nv_bfloat16* sBlo = csmem + 3 * CTILE;

    __shared__ int   s_cidx[GG][4];
    __shared__ float s_cw[GG][4];

    int n = blockIdx.x;
    int L = blockIdx.y;
    const float* tf = (L == 0) ? tf0 : (L == 1) ? tf1 : (L == 2) ? tf2 : tf3;

    int t = threadIdx.x;
    int wid = t >> 5;

    if (t < GG) {
        float scale = 1.0f / (float)(1 << L);
        float cx = coords[n * 2 + 0] * scale;
        float cy = coords[n * 2 + 1] * scale;
        int h = t / GDIM, w = t % GDIM;
        float fx = cx + (float)(h - 3);
        float fy = cy + (float)(w - 3);
        float x0f = floorf(fx), y0f = floorf(fy);
        float wx = fx - x0f, wy = fy - y0f;
        int x0 = (int)x0f, y0 = (int)y0f;
        int W = c_W[L], Hh = c_H[L];
        int base = c_pixoff[L];
#pragma unroll
        for (int k = 0; k < 4; k++) {
            int xi = x0 + (k & 1);
            int yi = y0 + (k >> 1);
            bool valid = (xi >= 0) && (xi < W) && (yi >= 0) && (yi < Hh);
            float wk = ((k & 1) ? wx : 1.0f - wx) * ((k >> 1) ? wy : 1.0f - wy);
            s_cidx[t][k] = valid ? (base + yi * W + xi) * 128 : 0;
            s_cw[t][k]   = valid ? wk : 0.0f;
        }
    }
    __syncthreads();

    // merged: B (tfeat rows) + A (bilinear gather), f32 -> bf16 hi/lo
    for (int idx = t; idx < GG * 32; idx += 256) {
        int row = idx >> 5;
        int seg = (idx & 31) * 4;

        float4 v = *(const float4*)&tf[((size_t)row * NPTS + n) * 128 + seg];
        __nv_bfloat16 h0 = __float2bfloat16(v.x), h1 = __float2bfloat16(v.y);
        __nv_bfloat16 h2 = __float2bfloat16(v.z), h3 = __float2bfloat16(v.w);
        __nv_bfloat16* bh = &sBhi[row * CLDS + seg];
        __nv_bfloat16* bl = &sBlo[row * CLDS + seg];
        bh[0] = h0; bh[1] = h1; bh[2] = h2; bh[3] = h3;
        bl[0] = __float2bfloat16(v.x - __bfloat162float(h0));
        bl[1] = __float2bfloat16(v.y - __bfloat162float(h1));
        bl[2] = __float2bfloat16(v.z - __bfloat162float(h2));
        bl[3] = __float2bfloat16(v.w - __bfloat162float(h3));

        float4 a = make_float4(0.f, 0.f, 0.f, 0.f);
#pragma unroll
        for (int k = 0; k < 4; k++) {
            float wk = s_cw[row][k];
            float4 g = *(const float4*)&g_fmapT[s_cidx[row][k] + seg];
            a.x += wk * g.x; a.y += wk * g.y; a.z += wk * g.z; a.w += wk * g.w;
        }
        __nv_bfloat16 a0 = __float2bfloat16(a.x), a1 = __float2bfloat16(a.y);
        __nv_bfloat16 a2 = __float2bfloat16(a.z), a3 = __float2bfloat16(a.w);
        __nv_bfloat16* ah = &sAhi[row * CLDS + seg];
        __nv_bfloat16* al = &sAlo[row * CLDS + seg];
        ah[0] = a0; ah[1] = a1; ah[2] = a2; ah[3] = a3;
        al[0] = __float2bfloat16(a.x - __bfloat162float(a0));
        al[1] = __float2bfloat16(a.y - __bfloat162float(a1));
        al[2] = __float2bfloat16(a.z - __bfloat162float(a2));
        al[3] = __float2bfloat16(a.w - __bfloat162float(a3));
    }
    __syncthreads();

    int wm = (wid & 3) * 16;
    int wn = (wid >> 2) * 32;
    wmma::fragment<wmma::accumulator, 16, 16, 16, float> acc[2];
    wmma::fill_fragment(acc[0], 0.0f);
    wmma::fill_fragment(acc[1], 0.0f);

#pragma unroll
    for (int ks = 0; ks < 8; ks++) {
        wmma::fragment<wmma::matrix_a, 16, 16, 16, __nv_bfloat16, wmma::row_major> ah, al;
        wmma::load_matrix_sync(ah, sAhi + wm * CLDS + ks * 16, CLDS);
        wmma::load_matrix_sync(al, sAlo + wm * CLDS + ks * 16, CLDS);
#pragma unroll
        for (int ni = 0; ni < 2; ni++) {
            wmma::fragment<wmma::matrix_b, 16, 16, 16, __nv_bfloat16, wmma::col_major> bh, bl;
            wmma::load_matrix_sync(bh, sBhi + (wn + ni * 16) * CLDS + ks * 16, CLDS);
            wmma::load_matrix_sync(bl, sBlo + (wn + ni * 16) * CLDS + ks * 16, CLDS);
            wmma::mma_sync(acc[ni], ah, bh, acc[ni]);
            wmma::mma_sync(acc[ni], al, bh, acc[ni]);
            wmma::mma_sync(acc[ni], ah, bl, acc[ni]);
        }
    }
    __syncthreads();

    float* stage = (float*)sAhi;
#pragma unroll
    for (int ni = 0; ni < 2; ni++)
        wmma::store_matrix_sync(stage + wm * 68 + wn + ni * 16, acc[ni], 68,
                                wmma::mem_row_major);
    __syncthreads();

    size_t xb = ((size_t)L * NPTS + n) * KPAD;
    for (int idx = t; idx < 2401; idx += 256) {
        int hw = idx / 49, ij = idx - hw * 49;
        float v = stage[hw * 68 + ij];
        __nv_bfloat16 hi = __float2bfloat16(v);
        g_Xhi[xb + idx] = hi;
        g_Xlo[xb + idx] = __float2bfloat16(v - __bfloat162float(hi));
    }
    if (t < KPAD - 2401) {
        g_Xhi[xb + 2401 + t] = __float2bfloat16(0.0f);
        g_Xlo[xb + 2401 + t] = __float2bfloat16(0.0f);
    }
}

// ---------------------------------------------------------------------------
// WMMA bf16 GEMM, 3-term hi/lo, cp.async 2-stage pipeline, 1 barrier/iter.
//   MLP1: A=g_X* [L][4096][2432], B=g_W1* [384][2432], GELU -> g_H* (bf16)
//   MLP2: A=g_H* [L][4096][384],  B=g_W2* [256][384],  bias  -> d_out f32
// ---------------------------------------------------------------------------
#define BK 32
#define LDS 40                       // BK + 8 pad (bf16)
#define TILE_E (128 * LDS)           // elems per tile
#define TILE_B (TILE_E * 2)          // bytes per tile
#define STAGE_B (4 * TILE_B)         // bytes per stage (40960)
#define MLP_SMEM (2 * STAGE_B)       // 81920 bytes

template <bool MLP1>
__global__ __launch_bounds__(256)
void wmma_gemm_kernel(const float* __restrict__ bias, float* __restrict__ outp) {
    constexpr int KTOT = MLP1 ? KPAD : HDIM;
    constexpr int NIT  = KTOT / BK;

    extern __shared__ __align__(16) __nv_bfloat16 dsmem[];
    uint32_t su = smem_to_u32(dsmem);

    int t   = threadIdx.x;
    int wid = t >> 5, lane = t & 31;
    int m0  = blockIdx.x * 128;
    int n0  = blockIdx.y * 128;
    int L   = blockIdx.z;

    const __nv_bfloat16* Ahi = (MLP1 ? g_Xhi : g_Hhi) + ((size_t)L * NPTS + m0) * KTOT;
    const __nv_bfloat16* Alo = (MLP1 ? g_Xlo : g_Hlo) + ((size_t)L * NPTS + m0) * KTOT;
    const __nv_bfloat16* Bhi = (MLP1 ? g_W1hi : g_W2hi) + (size_t)n0 * KTOT;
    const __nv_bfloat16* Blo = (MLP1 ? g_W1lo : g_W2lo) + (size_t)n0 * KTOT;
    const __nv_bfloat16* srcs[4] = {Ahi, Alo, Bhi, Blo};

    // per-thread chunk geometry: 2 chunks (16B) per tile per thread
    size_t rowoff[2]; uint32_t smbyte[2];
#pragma unroll
    for (int j = 0; j < 2; j++) {
        int p = t + 256 * j;
        int row = p >> 2, seg = p & 3;
        rowoff[j] = (size_t)row * KTOT + seg * 8;
        smbyte[j] = (uint32_t)(row * LDS + seg * 8) * 2;
    }

    wmma::fragment<wmma::accumulator, 16, 16, 16, float> acc[2][4];
#pragma unroll
    for (int mi = 0; mi < 2; mi++)
#pragma unroll
        for (int ni = 0; ni < 4; ni++) wmma::fill_fragment(acc[mi][ni], 0.0f);

    int wm = (wid & 3) * 32;
    int wn = (wid >> 2) * 64;

    // prologue: stage 0
#pragma unroll
    for (int tile = 0; tile < 4; tile++)
#pragma unroll
        for (int j = 0; j < 2; j++)
            cp16(su + tile * TILE_B + smbyte[j], srcs[tile] + rowoff[j]);
    CP_COMMIT();

    for (int kt = 0; kt < NIT; kt++) {
        CP_WAIT0();
        __syncthreads();

        if (kt + 1 < NIT) {
            int kc = (kt + 1) * BK;
            uint32_t sb = su + ((kt + 1) & 1) * STAGE_B;
#pragma unroll
            for (int tile = 0; tile < 4; tile++)
#pragma unroll
                for (int j = 0; j < 2; j++)
                    cp16(sb + tile * TILE_B + smbyte[j], srcs[tile] + kc + rowoff[j]);
            CP_COMMIT();
        }

        const __nv_bfloat16* sbase = dsmem + (kt & 1) * (4 * TILE_E);
        const __nv_bfloat16* sAhi = sbase;
        const __nv_bfloat16* sAlo = sbase + TILE_E;
        const __nv_bfloat16* sBhi = sbase + 2 * TILE_E;
        const __nv_bfloat16* sBlo = sbase + 3 * TILE_E;

#pragma unroll
        for (int kk = 0; kk < 2; kk++) {
            wmma::fragment<wmma::matrix_a, 16, 16, 16, __nv_bfloat16, wmma::row_major> ah[2], al[2];
#pragma unroll
            for (int mi = 0; mi < 2; mi++) {
                wmma::load_matrix_sync(ah[mi], sAhi + (wm + mi * 16) * LDS + kk * 16, LDS);
                wmma::load_matrix_sync(al[mi], sAlo + (wm + mi * 16) * LDS + kk * 16, LDS);
            }
#pragma unroll
            for (int ni = 0; ni < 4; ni++) {
                wmma::fragment<wmma::matrix_b, 16, 16, 16, __nv_bfloat16, wmma::col_major> bh, bl;
                wmma::load_matrix_sync(bh, sBhi + (wn + ni * 16) * LDS + kk * 16, LDS);
                wmma::load_matrix_sync(bl, sBlo + (wn + ni * 16) * LDS + kk * 16, LDS);
#pragma unroll
                for (int mi = 0; mi < 2; mi++) {
                    wmma::mma_sync(acc[mi][ni], ah[mi], bh, acc[mi][ni]);
                    wmma::mma_sync(acc[mi][ni], al[mi], bh, acc[mi][ni]);
                    wmma::mma_sync(acc[mi][ni], ah[mi], bl, acc[mi][ni]);
                }
            }
        }
    }
    __syncthreads();

    // epilogue: per-warp staging in buffer 0 (last mma stage was buffer 1 when
    // NIT even; distinct 1KB regions per warp regardless).
    float* stage = (float*)dsmem + wid * 256;
    int r = lane >> 1;
    int c = (lane & 1) * 8;
#pragma unroll
    for (int mi = 0; mi < 2; mi++)
#pragma unroll
        for (int ni = 0; ni < 4; ni++) {
            wmma::store_matrix_sync(stage, acc[mi][ni], 16, wmma::mem_row_major);
            __syncwarp();
            int grow = m0 + wm + mi * 16 + r;
            int gcol = n0 + wn + ni * 16 + c;
            float v[8];
#pragma unroll
            for (int u = 0; u < 8; u++) {
                float x = stage[r * 16 + c + u] + bias[gcol + u];
                if (MLP1) x = x * normcdff(x);
                v[u] = x;
            }
            if (MLP1) {
                __nv_bfloat16 hi8[8], lo8[8];
#pragma unroll
                for (int u = 0; u < 8; u++) {
                    __nv_bfloat16 hi = __float2bfloat16(v[u]);
                    hi8[u] = hi;
                    lo8[u] = __float2bfloat16(v[u] - __bfloat162float(hi));
                }
                size_t hidx = ((size_t)L * NPTS + grow) * HDIM + gcol;
                *(uint4*)&g_Hhi[hidx] = *(uint4*)hi8;
                *(uint4*)&g_Hlo[hidx] = *(uint4*)lo8;
            } else {
                float* dst = &outp[(size_t)grow * 1024 + L * ODIM + gcol];
                *(float4*)dst       = *(float4*)(v);
                *(float4*)(dst + 4) = *(float4*)(v + 4);
            }
            __syncwarp();
        }
}

// ---------------------------------------------------------------------------
// launch
// ---------------------------------------------------------------------------
extern "C" void kernel_launch(void* const* d_in, const int* in_sizes, int n_in,
                              void* d_out, int out_size) {
    (void)out_size;
    const float* fmaps[4] = {nullptr, nullptr, nullptr, nullptr};
    const float* tfeat[4] = {nullptr, nullptr, nullptr, nullptr};
    const float *coords = nullptr, *w1 = nullptr, *b1 = nullptr, *w2 = nullptr, *b2 = nullptr;
    int tc = 0;
    bool seen98 = false;
    for (int i = 0; i < n_in; i++) {
        int s = in_sizes[i];
        const float* p = (const float*)d_in[i];
        if (s == 1572864)       fmaps[0] = p;
        else if (s == 393216)   fmaps[1] = p;
        else if (s == 24576)    fmaps[3] = p;
        else if (s == 25690112) { if (tc < 4) tfeat[tc++] = p; }
        else if (s == 8192)     coords = p;
        else if (s == 921984)   w1 = p;
        else if (s == 384)      b1 = p;
        else if (s == 256)      b2 = p;
        else if (s == 98304)    { if (!seen98) { fmaps[2] = p; seen98 = true; } else w2 = p; }
    }

    static const int hHs[4] = {96, 48, 24, 12};
    static const int hWs[4] = {128, 64, 32, 16};
    static const int hPixOff[4] = {0, 12288, 15360, 16128};

    cudaFuncSetAttribute(corr_wmma_kernel,
                         cudaFuncAttributeMaxDynamicSharedMemorySize, CORR_SMEM);
    cudaFuncSetAttribute(wmma_gemm_kernel<true>,
                         cudaFuncAttributeMaxDynamicSharedMemorySize, MLP_SMEM);
    cudaFuncSetAttribute(wmma_gemm_kernel<false>,
                         cudaFuncAttributeMaxDynamicSharedMemorySize, MLP_SMEM);

    dim3 tb(32, 32);
    for (int L = 0; L < 4; L++) {
        int HW = hHs[L] * hWs[L];
        transpose_kernel<<<dim3((HW + 31) / 32, 4), tb>>>(fmaps[L], HW, hPixOff[L]);
    }

    prep_w1_kernel<<<(HDIM * KPAD + 255) / 256, 256>>>(w1);
    prep_w2_kernel<<<(ODIM * HDIM + 255) / 256, 256>>>(w2);

    corr_wmma_kernel<<<dim3(NPTS, NLEV), 256, CORR_SMEM>>>(
        coords, tfeat[0], tfeat[1], tfeat[2], tfeat[3]);

    wmma_gemm_kernel<true><<<dim3(NPTS / 128, HDIM / 128, NLEV), 256, MLP_SMEM>>>(
        b1, nullptr);

    wmma_gemm_kernel<false><<<dim3(NPTS / 128, ODIM / 128, NLEV), 256, MLP_SMEM>>>(
        b2, (float*)d_out);
}

// round 7
// speedup vs baseline: 2.3758x; 1.0057x over previous
#include <cuda_runtime.h>
#include <cuda_bf16.h>
#include <mma.h>
#include <cstdint>
#include <math.h>

using namespace nvcuda;

// ---------------------------------------------------------------------------
// LiteTracker correlation pyramid, round 7 (= round 6 + setup-loop bugfix):
//   transpose -> corr WMMA bf16 (8 points/block, register-prefetch pipeline)
//   -> MLP1 WMMA + cp.async -> MLP2 -> out.
// ---------------------------------------------------------------------------

#define GDIM 7
#define GG 49
#define CDIM 128
#define NPTS 4096
#define NLEV 4
#define KPAD 2432          // 2401 padded to 76*32
#define HDIM 384
#define ODIM 256
#define PPB 8              // points per corr block

// ------------------------------ level geometry -----------------------------
__constant__ int c_H[4]      = {96, 48, 24, 12};
__constant__ int c_W[4]      = {128, 64, 32, 16};
__constant__ int c_pixoff[4] = {0, 12288, 15360, 16128};

// ------------------------------ device scratch -----------------------------
__device__ __align__(16) float g_fmapT[16320 * 128];
__device__ __align__(16) __nv_bfloat16 g_Xhi[(size_t)NLEV * NPTS * KPAD];
__device__ __align__(16) __nv_bfloat16 g_Xlo[(size_t)NLEV * NPTS * KPAD];
__device__ __align__(16) __nv_bfloat16 g_W1hi[HDIM * KPAD];
__device__ __align__(16) __nv_bfloat16 g_W1lo[HDIM * KPAD];
__device__ __align__(16) __nv_bfloat16 g_W2hi[ODIM * HDIM];
__device__ __align__(16) __nv_bfloat16 g_W2lo[ODIM * HDIM];
__device__ __align__(16) __nv_bfloat16 g_Hhi[(size_t)NLEV * NPTS * HDIM];
__device__ __align__(16) __nv_bfloat16 g_Hlo[(size_t)NLEV * NPTS * HDIM];

// ------------------------------ cp.async helpers ---------------------------
__device__ __forceinline__ uint32_t smem_to_u32(const void* p) {
    uint32_t a;
    asm("{ .reg .u64 t; cvta.to.shared.u64 t, %1; cvt.u32.u64 %0, t; }"
        : "=r"(a) : "l"(p));
    return a;
}
__device__ __forceinline__ void cp16(uint32_t dst, const void* src) {
    asm volatile("cp.async.cg.shared.global [%0], [%1], 16;" :: "r"(dst), "l"(src));
}
#define CP_COMMIT() asm volatile("cp.async.commit_group;" ::: "memory")
#define CP_WAIT0()  asm volatile("cp.async.wait_group 0;" ::: "memory")

// ---------------------------------------------------------------------------
// Kernel T: fmap [128, H, W] -> fmapT [(H*W), 128]
// ---------------------------------------------------------------------------
__global__ void transpose_kernel(const float* __restrict__ src, int HW, int pixoff) {
    __shared__ float tile[32][33];
    int pix0 = blockIdx.x * 32;
    int ch0  = blockIdx.y * 32;
    int tx = threadIdx.x, ty = threadIdx.y;
    int pix = pix0 + tx;
    if (pix < HW) tile[ty][tx] = src[(ch0 + ty) * HW + pix];
    __syncthreads();
    int opix = pix0 + ty;
    int och  = ch0 + tx;
    if (opix < HW) g_fmapT[(size_t)(pixoff + opix) * 128 + och] = tile[tx][ty];
}

// ---------------------------------------------------------------------------
// Weight prep
// ---------------------------------------------------------------------------
__global__ void prep_w1_kernel(const float* __restrict__ w1) {
    int idx = blockIdx.x * 256 + threadIdx.x;
    if (idx >= HDIM * KPAD) return;
    int n = idx / KPAD, k = idx % KPAD;
    float v = (k < 2401) ? w1[k * HDIM + n] : 0.0f;
    __nv_bfloat16 hi = __float2bfloat16(v);
    g_W1hi[idx] = hi;
    g_W1lo[idx] = __float2bfloat16(v - __bfloat162float(hi));
}

__global__ void prep_w2_kernel(const float* __restrict__ w2) {
    int idx = blockIdx.x * 256 + threadIdx.x;
    if (idx >= ODIM * HDIM) return;
    int n = idx / HDIM, k = idx % HDIM;
    float v = w2[k * ODIM + n];
    __nv_bfloat16 hi = __float2bfloat16(v);
    g_W2hi[idx] = hi;
    g_W2lo[idx] = __float2bfloat16(v - __bfloat162float(hi));
}

// ---------------------------------------------------------------------------
// Kernel C (WMMA, pipelined): block handles PPB points at one level.
// ---------------------------------------------------------------------------
#define CLDS 136                       // 128 + 8 pad (bf16 elems)
#define CTILE (64 * CLDS)              // one 64x128 tile (elems)
#define CORR_TILES_B (4 * CTILE * 2)   // 69632 bytes
#define CORR_STAGE_B (64 * 68 * 4)     // 17408 bytes
#define CORR_SMEM (CORR_TILES_B + CORR_STAGE_B)
#define NCHUNK 7                       // ceil(1568/256) 16B chunks per thread

__global__ __launch_bounds__(256)
void corr_wmma_kernel(const float* __restrict__ coords,
                      const float* __restrict__ tf0, const float* __restrict__ tf1,
                      const float* __restrict__ tf2, const float* __restrict__ tf3) {
    extern __shared__ __align__(16) char csmem[];
    __nv_bfloat16* sAhi = (__nv_bfloat16*)csmem;
    __nv_bfloat16* sAlo = sAhi + CTILE;
    __nv_bfloat16* sBhi = sAhi + 2 * CTILE;
    __nv_bfloat16* sBlo = sAhi + 3 * CTILE;
    float* Cstage = (float*)(csmem + CORR_TILES_B);

    __shared__ int   s_cidx[PPB][GG][4];
    __shared__ float s_cw[PPB][GG][4];

    int n0 = blockIdx.x * PPB;
    int L  = blockIdx.y;
    const float* tf = (L == 0) ? tf0 : (L == 1) ? tf1 : (L == 2) ? tf2 : tf3;

    int t = threadIdx.x;
    int wid = t >> 5;

    // precompute bilinear corner indices + weights for ALL PPB*GG pairs
    // (strided loop — 392 > 256 threads, so a single if(t<...) is NOT enough)
    for (int idx = t; idx < PPB * GG; idx += 256) {
        int p = idx / GG, s = idx - p * GG;
        float scale = 1.0f / (float)(1 << L);
        float cx = coords[(n0 + p) * 2 + 0] * scale;
        float cy = coords[(n0 + p) * 2 + 1] * scale;
        int h = s / GDIM, w = s % GDIM;
        float fx = cx + (float)(h - 3);
        float fy = cy + (float)(w - 3);
        float x0f = floorf(fx), y0f = floorf(fy);
        float wx = fx - x0f, wy = fy - y0f;
        int x0 = (int)x0f, y0 = (int)y0f;
        int W = c_W[L], Hh = c_H[L];
        int base = c_pixoff[L];
#pragma unroll
        for (int k = 0; k < 4; k++) {
            int xi = x0 + (k & 1);
            int yi = y0 + (k >> 1);
            bool valid = (xi >= 0) && (xi < W) && (yi >= 0) && (yi < Hh);
            float wk = ((k & 1) ? wx : 1.0f - wx) * ((k >> 1) ? wy : 1.0f - wy);
            s_cidx[p][s][k] = valid ? (base + yi * W + xi) * 128 : 0;
            s_cw[p][s][k]   = valid ? wk : 0.0f;
        }
    }

    // per-thread tfeat chunk geometry (fixed across points)
    int ch_row[NCHUNK], ch_seg[NCHUNK];
#pragma unroll
    for (int j = 0; j < NCHUNK; j++) {
        int chunk = t + 256 * j;
        ch_row[j] = chunk >> 5;             // support sample
        ch_seg[j] = (chunk & 31) * 4;       // float offset within 128
    }

    // prefetch tfeat for point 0
    float4 pre[NCHUNK];
#pragma unroll
    for (int j = 0; j < NCHUNK; j++) {
        int chunk = t + 256 * j;
        if (chunk < GG * 32)
            pre[j] = *(const float4*)&tf[((size_t)ch_row[j] * NPTS + n0) * 128 + ch_seg[j]];
    }
    __syncthreads();   // cidx/cw ready

    int wm = (wid & 3) * 16;
    int wn = (wid >> 2) * 32;

    for (int p = 0; p < PPB; p++) {
        int n = n0 + p;

        // convert prefetched tfeat -> B tiles (hi/lo)
#pragma unroll
        for (int j = 0; j < NCHUNK; j++) {
            int chunk = t + 256 * j;
            if (chunk < GG * 32) {
                float4 v = pre[j];
                int row = ch_row[j], seg = ch_seg[j];
                __nv_bfloat16 h0 = __float2bfloat16(v.x), h1 = __float2bfloat16(v.y);
                __nv_bfloat16 h2 = __float2bfloat16(v.z), h3 = __float2bfloat16(v.w);
                __nv_bfloat16* bh = &sBhi[row * CLDS + seg];
                __nv_bfloat16* bl = &sBlo[row * CLDS + seg];
                bh[0] = h0; bh[1] = h1; bh[2] = h2; bh[3] = h3;
                bl[0] = __float2bfloat16(v.x - __bfloat162float(h0));
                bl[1] = __float2bfloat16(v.y - __bfloat162float(h1));
                bl[2] = __float2bfloat16(v.z - __bfloat162float(h2));
                bl[3] = __float2bfloat16(v.w - __bfloat162float(h3));
            }
        }

        // bilinear gather -> A tiles (hi/lo)
#pragma unroll
        for (int j = 0; j < NCHUNK; j++) {
            int chunk = t + 256 * j;
            if (chunk < GG * 32) {
                int row = ch_row[j], seg = ch_seg[j];
                float4 a = make_float4(0.f, 0.f, 0.f, 0.f);
#pragma unroll
                for (int k = 0; k < 4; k++) {
                    float wk = s_cw[p][row][k];
                    float4 g = *(const float4*)&g_fmapT[s_cidx[p][row][k] + seg];
                    a.x += wk * g.x; a.y += wk * g.y; a.z += wk * g.z; a.w += wk * g.w;
                }
                __nv_bfloat16 a0 = __float2bfloat16(a.x), a1 = __float2bfloat16(a.y);
                __nv_bfloat16 a2 = __float2bfloat16(a.z), a3 = __float2bfloat16(a.w);
                __nv_bfloat16* ah = &sAhi[row * CLDS + seg];
                __nv_bfloat16* al = &sAlo[row * CLDS + seg];
                ah[0] = a0; ah[1] = a1; ah[2] = a2; ah[3] = a3;
                al[0] = __float2bfloat16(a.x - __bfloat162float(a0));
                al[1] = __float2bfloat16(a.y - __bfloat162float(a1));
                al[2] = __float2bfloat16(a.z - __bfloat162float(a2));
                al[3] = __float2bfloat16(a.w - __bfloat162float(a3));
            }
        }
        __syncthreads();   // S1: tiles ready

        // prefetch tfeat for next point (overlaps mma + write below)
        if (p + 1 < PPB) {
#pragma unroll
            for (int j = 0; j < NCHUNK; j++) {
                int chunk = t + 256 * j;
                if (chunk < GG * 32)
                    pre[j] = *(const float4*)
                        &tf[((size_t)ch_row[j] * NPTS + n + 1) * 128 + ch_seg[j]];
            }
        }

        // MMA: C[64x64] = Ahi*Bhi^T + Alo*Bhi^T + Ahi*Blo^T
        wmma::fragment<wmma::accumulator, 16, 16, 16, float> acc[2];
        wmma::fill_fragment(acc[0], 0.0f);
        wmma::fill_fragment(acc[1], 0.0f);
#pragma unroll
        for (int ks = 0; ks < 8; ks++) {
            wmma::fragment<wmma::matrix_a, 16, 16, 16, __nv_bfloat16, wmma::row_major> ah, al;
            wmma::load_matrix_sync(ah, sAhi + wm * CLDS + ks * 16, CLDS);
            wmma::load_matrix_sync(al, sAlo + wm * CLDS + ks * 16, CLDS);
#pragma unroll
            for (int ni = 0; ni < 2; ni++) {
                wmma::fragment<wmma::matrix_b, 16, 16, 16, __nv_bfloat16, wmma::col_major> bh, bl;
                wmma::load_matrix_sync(bh, sBhi + (wn + ni * 16) * CLDS + ks * 16, CLDS);
                wmma::load_matrix_sync(bl, sBlo + (wn + ni * 16) * CLDS + ks * 16, CLDS);
                wmma::mma_sync(acc[ni], ah, bh, acc[ni]);
                wmma::mma_sync(acc[ni], al, bh, acc[ni]);
                wmma::mma_sync(acc[ni], ah, bl, acc[ni]);
            }
        }
        __syncthreads();   // S2: tile reads done (and prior Cstage reads done)

#pragma unroll
        for (int ni = 0; ni < 2; ni++)
            wmma::store_matrix_sync(Cstage + wm * 68 + wn + ni * 16, acc[ni], 68,
                                    wmma::mem_row_major);
        __syncthreads();   // S3: Cstage ready

        // write X row (hi/lo) + zero pad
        size_t xb = ((size_t)L * NPTS + n) * KPAD;
        for (int idx = t; idx < 2401; idx += 256) {
            int hw = idx / 49, ij = idx - hw * 49;
            float v = Cstage[hw * 68 + ij];
            __nv_bfloat16 hi = __float2bfloat16(v);
            g_Xhi[xb + idx] = hi;
            g_Xlo[xb + idx] = __float2bfloat16(v - __bfloat162float(hi));
        }
        if (t < KPAD - 2401) {
            g_Xhi[xb + 2401 + t] = __float2bfloat16(0.0f);
            g_Xlo[xb + 2401 + t] = __float2bfloat16(0.0f);
        }
    }
}

// ---------------------------------------------------------------------------
// WMMA bf16 GEMM, 3-term hi/lo, cp.async 2-stage pipeline (unchanged from R5).
// ---------------------------------------------------------------------------
#define BK 32
#define LDS 40
#define TILE_E (128 * LDS)
#define TILE_B (TILE_E * 2)
#define STAGE_B (4 * TILE_B)
#define MLP_SMEM (2 * STAGE_B)

template <bool MLP1>
__global__ __launch_bounds__(256)
void wmma_gemm_kernel(const float* __restrict__ bias, float* __restrict__ outp) {
    constexpr int KTOT = MLP1 ? KPAD : HDIM;
    constexpr int NIT  = KTOT / BK;

    extern __shared__ __align__(16) __nv_bfloat16 dsmem[];
    uint32_t su = smem_to_u32(dsmem);

    int t   = threadIdx.x;
    int wid = t >> 5, lane = t & 31;
    int m0  = blockIdx.x * 128;
    int n0  = blockIdx.y * 128;
    int L   = blockIdx.z;

    const __nv_bfloat16* Ahi = (MLP1 ? g_Xhi : g_Hhi) + ((size_t)L * NPTS + m0) * KTOT;
    const __nv_bfloat16* Alo = (MLP1 ? g_Xlo : g_Hlo) + ((size_t)L * NPTS + m0) * KTOT;
    const __nv_bfloat16* Bhi = (MLP1 ? g_W1hi : g_W2hi) + (size_t)n0 * KTOT;
    const __nv_bfloat16* Blo = (MLP1 ? g_W1lo : g_W2lo) + (size_t)n0 * KTOT;
    const __nv_bfloat16* srcs[4] = {Ahi, Alo, Bhi, Blo};

    size_t rowoff[2]; uint32_t smbyte[2];
#pragma unroll
    for (int j = 0; j < 2; j++) {
        int p = t + 256 * j;
        int row = p >> 2, seg = p & 3;
        rowoff[j] = (size_t)row * KTOT + seg * 8;
        smbyte[j] = (uint32_t)(row * LDS + seg * 8) * 2;
    }

    wmma::fragment<wmma::accumulator, 16, 16, 16, float> acc[2][4];
#pragma unroll
    for (int mi = 0; mi < 2; mi++)
#pragma unroll
        for (int ni = 0; ni < 4; ni++) wmma::fill_fragment(acc[mi][ni], 0.0f);

    int wm = (wid & 3) * 32;
    int wn = (wid >> 2) * 64;

#pragma unroll
    for (int tile = 0; tile < 4; tile++)
#pragma unroll
        for (int j = 0; j < 2; j++)
            cp16(su + tile * TILE_B + smbyte[j], srcs[tile] + rowoff[j]);
    CP_COMMIT();

    for (int kt = 0; kt < NIT; kt++) {
        CP_WAIT0();
        __syncthreads();

        if (kt + 1 < NIT) {
            int kc = (kt + 1) * BK;
            uint32_t sb = su + ((kt + 1) & 1) * STAGE_B;
#pragma unroll
            for (int tile = 0; tile < 4; tile++)
#pragma unroll
                for (int j = 0; j < 2; j++)
                    cp16(sb + tile * TILE_B + smbyte[j], srcs[tile] + kc + rowoff[j]);
            CP_COMMIT();
        }

        const __nv_bfloat16* sbase = dsmem + (kt & 1) * (4 * TILE_E);
        const __nv_bfloat16* sAhi = sbase;
        const __nv_bfloat16* sAlo = sbase + TILE_E;
        const __nv_bfloat16* sBhi = sbase + 2 * TILE_E;
        const __nv_bfloat16* sBlo = sbase + 3 * TILE_E;

#pragma unroll
        for (int kk = 0; kk < 2; kk++) {
            wmma::fragment<wmma::matrix_a, 16, 16, 16, __nv_bfloat16, wmma::row_major> ah[2], al[2];
#pragma unroll
            for (int mi = 0; mi < 2; mi++) {
                wmma::load_matrix_sync(ah[mi], sAhi + (wm + mi * 16) * LDS + kk * 16, LDS);
                wmma::load_matrix_sync(al[mi], sAlo + (wm + mi * 16) * LDS + kk * 16, LDS);
            }
#pragma unroll
            for (int ni = 0; ni < 4; ni++) {
                wmma::fragment<wmma::matrix_b, 16, 16, 16, __nv_bfloat16, wmma::col_major> bh, bl;
                wmma::load_matrix_sync(bh, sBhi + (wn + ni * 16) * LDS + kk * 16, LDS);
                wmma::load_matrix_sync(bl, sBlo + (wn + ni * 16) * LDS + kk * 16, LDS);
#pragma unroll
                for (int mi = 0; mi < 2; mi++) {
                    wmma::mma_sync(acc[mi][ni], ah[mi], bh, acc[mi][ni]);
                    wmma::mma_sync(acc[mi][ni], al[mi], bh, acc[mi][ni]);
                    wmma::mma_sync(acc[mi][ni], ah[mi], bl, acc[mi][ni]);
                }
            }
        }
    }
    __syncthreads();

    float* stage = (float*)dsmem + wid * 256;
    int r = lane >> 1;
    int c = (lane & 1) * 8;
#pragma unroll
    for (int mi = 0; mi < 2; mi++)
#pragma unroll
        for (int ni = 0; ni < 4; ni++) {
            wmma::store_matrix_sync(stage, acc[mi][ni], 16, wmma::mem_row_major);
            __syncwarp();
            int grow = m0 + wm + mi * 16 + r;
            int gcol = n0 + wn + ni * 16 + c;
            float v[8];
#pragma unroll
            for (int u = 0; u < 8; u++) {
                float x = stage[r * 16 + c + u] + bias[gcol + u];
                if (MLP1) x = x * normcdff(x);
                v[u] = x;
            }
            if (MLP1) {
                __nv_bfloat16 hi8[8], lo8[8];
#pragma unroll
                for (int u = 0; u < 8; u++) {
                    __nv_bfloat16 hi = __float2bfloat16(v[u]);
                    hi8[u] = hi;
                    lo8[u] = __float2bfloat16(v[u] - __bfloat162float(hi));
                }
                size_t hidx = ((size_t)L * NPTS + grow) * HDIM + gcol;
                *(uint4*)&g_Hhi[hidx] = *(uint4*)hi8;
                *(uint4*)&g_Hlo[hidx] = *(uint4*)lo8;
            } else {
                float* dst = &outp[(size_t)grow * 1024 + L * ODIM + gcol];
                *(float4*)dst       = *(float4*)(v);
                *(float4*)(dst + 4) = *(float4*)(v + 4);
            }
            __syncwarp();
        }
}

// ---------------------------------------------------------------------------
// launch
// ---------------------------------------------------------------------------
extern "C" void kernel_launch(void* const* d_in, const int* in_sizes, int n_in,
                              void* d_out, int out_size) {
    (void)out_size;
    const float* fmaps[4] = {nullptr, nullptr, nullptr, nullptr};
    const float* tfeat[4] = {nullptr, nullptr, nullptr, nullptr};
    const float *coords = nullptr, *w1 = nullptr, *b1 = nullptr, *w2 = nullptr, *b2 = nullptr;
    int tc = 0;
    bool seen98 = false;
    for (int i = 0; i < n_in; i++) {
        int s = in_sizes[i];
        const float* p = (const float*)d_in[i];
        if (s == 1572864)       fmaps[0] = p;
        else if (s == 393216)   fmaps[1] = p;
        else if (s == 24576)    fmaps[3] = p;
        else if (s == 25690112) { if (tc < 4) tfeat[tc++] = p; }
        else if (s == 8192)     coords = p;
        else if (s == 921984)   w1 = p;
        else if (s == 384)      b1 = p;
        else if (s == 256)      b2 = p;
        else if (s == 98304)    { if (!seen98) { fmaps[2] = p; seen98 = true; } else w2 = p; }
    }

    static const int hHs[4] = {96, 48, 24, 12};
    static const int hWs[4] = {128, 64, 32, 16};
    static const int hPixOff[4] = {0, 12288, 15360, 16128};

    cudaFuncSetAttribute(corr_wmma_kernel,
                         cudaFuncAttributeMaxDynamicSharedMemorySize, CORR_SMEM);
    cudaFuncSetAttribute(wmma_gemm_kernel<true>,
                         cudaFuncAttributeMaxDynamicSharedMemorySize, MLP_SMEM);
    cudaFuncSetAttribute(wmma_gemm_kernel<false>,
                         cudaFuncAttributeMaxDynamicSharedMemorySize, MLP_SMEM);

    dim3 tb(32, 32);
    for (int L = 0; L < 4; L++) {
        int HW = hHs[L] * hWs[L];
        transpose_kernel<<<dim3((HW + 31) / 32, 4), tb>>>(fmaps[L], HW, hPixOff[L]);
    }

    prep_w1_kernel<<<(HDIM * KPAD + 255) / 256, 256>>>(w1);
    prep_w2_kernel<<<(ODIM * HDIM + 255) / 256, 256>>>(w2);

    corr_wmma_kernel<<<dim3(NPTS / PPB, NLEV), 256, CORR_SMEM>>>(
        coords, tfeat[0], tfeat[1], tfeat[2], tfeat[3]);

    wmma_gemm_kernel<true><<<dim3(NPTS / 128, HDIM / 128, NLEV), 256, MLP_SMEM>>>(
        b1, nullptr);

    wmma_gemm_kernel<false><<<dim3(NPTS / 128, ODIM / 128, NLEV), 256, MLP_SMEM>>>(
        b2, (float*)d_out);
}